// round 17
// baseline (speedup 1.0000x reference)
#include <cuda_runtime.h>
#include <cuda_fp16.h>

#define D       64
#define DV      16          // uint2 (4-half) chunks per row
#define MAX_N   100000
#define MAX_E   1700000
#define NB      128         // persistent grid: <= SM count -> all resident
#define TB      1024
#define XS      72          // smem row stride in halves (bank-conflict-free)

// ---------------------------------------------------------------------------
// Device-global scratch. g_cnt zero at load, restored each run (read-clear).
// Barrier gen/cnt self-restoring across graph replays.
// ---------------------------------------------------------------------------
__device__ int    g_cnt[MAX_N];
__device__ int    g_off[MAX_N + 1];
__device__ int    g_pos[MAX_N];
__device__ int    g_bsum[NB];
__device__ int2   g_edge[MAX_E];
__device__ uint2  g_Yh[MAX_N * DV];    // Y = X @ W^T in fp16

__device__ volatile unsigned g_bar_gen;
__device__ unsigned          g_bar_cnt;

__device__ __forceinline__ void grid_barrier() {
    __syncthreads();
    if (threadIdx.x == 0) {
        unsigned gen = g_bar_gen;
        __threadfence();
        unsigned my = atomicAdd(&g_bar_cnt, 1u);
        if (my == gridDim.x - 1) {
            g_bar_cnt = 0;
            __threadfence();
            g_bar_gen = gen + 1;
        } else {
            while (g_bar_gen == gen) { }
            __threadfence();
        }
    }
    __syncthreads();
}

// ---------------------------------------------------------------------------
// CSR build: hist -> chunk scan -> prefix apply -> bin. R8 structure with
// batch-4 MLP on hist and bin (batched loops correctness-proven in R16).
// ---------------------------------------------------------------------------
__global__ __launch_bounds__(TB, 2) void csr_build_kernel(
    const int* __restrict__ row, const int* __restrict__ col,
    const float* __restrict__ vals, int E, int N)
{
    const int tid    = threadIdx.x;
    const int bid    = blockIdx.x;
    const int gtid   = bid * TB + tid;
    const int stride = NB * TB;            // 131072
    const int nch    = (N + TB - 1) / TB;  // 98 chunks of 1024

    // ---- Phase 1: histogram (batch 4 for MLP) ----
    {
        int e = gtid;
        for (; e + 3 * stride < E; e += 4 * stride) {
            int r0 = __ldg(row + e);
            int r1 = __ldg(row + e + stride);
            int r2 = __ldg(row + e + 2 * stride);
            int r3 = __ldg(row + e + 3 * stride);
            atomicAdd(&g_cnt[r0], 1);
            atomicAdd(&g_cnt[r1], 1);
            atomicAdd(&g_cnt[r2], 1);
            atomicAdd(&g_cnt[r3], 1);
        }
        for (; e < E; e += stride)
            atomicAdd(&g_cnt[__ldg(row + e)], 1);
    }

    grid_barrier();

    // ---- Phase 2: per-chunk exclusive scan ----
    __shared__ int wsum[32];
    if (bid < nch) {
        int i = bid * TB + tid;
        int v = 0;
        if (i < N) { v = g_cnt[i]; g_cnt[i] = 0; }   // read + restore invariant

        int lane = tid & 31;
        int wid  = tid >> 5;

        int s = v;
#pragma unroll
        for (int d = 1; d < 32; d <<= 1) {
            int t = __shfl_up_sync(0xFFFFFFFFu, s, d);
            if (lane >= d) s += t;
        }
        if (lane == 31) wsum[wid] = s;
        __syncthreads();
        if (wid == 0) {
            int ws = wsum[lane];
#pragma unroll
            for (int d = 1; d < 32; d <<= 1) {
                int t = __shfl_up_sync(0xFFFFFFFFu, ws, d);
                if (lane >= d) ws += t;
            }
            wsum[lane] = ws;
        }
        __syncthreads();
        int incl = s + (wid == 0 ? 0 : wsum[wid - 1]);
        if (i < N) g_off[i] = incl - v;
        if (tid == TB - 1) g_bsum[bid] = incl;
    }

    grid_barrier();

    // ---- Phase 3: add chunk prefix, init cursors ----
    __shared__ int s_part[4];
    __shared__ int s_pref;
    if (bid < nch) {
        if (tid < 128) {
            int vp = (tid < bid) ? g_bsum[tid] : 0;
#pragma unroll
            for (int d = 16; d >= 1; d >>= 1)
                vp += __shfl_down_sync(0xFFFFFFFFu, vp, d);
            if ((tid & 31) == 0) s_part[tid >> 5] = vp;
        }
        __syncthreads();
        if (tid == 0)
            s_pref = s_part[0] + s_part[1] + s_part[2] + s_part[3];
        __syncthreads();

        int i = bid * TB + tid;
        if (i < N) {
            int o = g_off[i] + s_pref;
            g_off[i] = o;
            g_pos[i] = o;
        }
    }
    if (bid == 0 && tid == 0) g_off[N] = E;

    grid_barrier();

    // ---- Phase 4: bin edges (batch 4 for MLP) ----
    {
        int e = gtid;
        for (; e + 3 * stride < E; e += 4 * stride) {
            int e1 = e + stride, e2 = e + 2 * stride, e3 = e + 3 * stride;
            int   r0 = __ldg(row + e),  r1 = __ldg(row + e1);
            int   r2 = __ldg(row + e2), r3 = __ldg(row + e3);
            int   c0 = __ldg(col + e),  c1 = __ldg(col + e1);
            int   c2 = __ldg(col + e2), c3 = __ldg(col + e3);
            float v0 = __ldg(vals + e),  v1 = __ldg(vals + e1);
            float v2 = __ldg(vals + e2), v3 = __ldg(vals + e3);
            int p0 = atomicAdd(&g_pos[r0], 1);
            int p1 = atomicAdd(&g_pos[r1], 1);
            int p2 = atomicAdd(&g_pos[r2], 1);
            int p3 = atomicAdd(&g_pos[r3], 1);
            g_edge[p0] = make_int2(c0, __float_as_int(v0));
            g_edge[p1] = make_int2(c1, __float_as_int(v1));
            g_edge[p2] = make_int2(c2, __float_as_int(v2));
            g_edge[p3] = make_int2(c3, __float_as_int(v3));
        }
        for (; e < E; e += stride) {
            int r = __ldg(row + e);
            int p = atomicAdd(&g_pos[r], 1);
            g_edge[p] = make_int2(__ldg(col + e),
                                  __float_as_int(__ldg(vals + e)));
        }
    }
}

// ---------------------------------------------------------------------------
// xform via tensor cores: Yh = fp16( X @ W^T ).  (R13-proven, unchanged.)
// ---------------------------------------------------------------------------
__device__ __forceinline__ void mma16816(
    float& d0, float& d1, float& d2, float& d3,
    unsigned a0, unsigned a1, unsigned a2, unsigned a3,
    unsigned b0, unsigned b1)
{
    asm volatile(
        "mma.sync.aligned.m16n8k16.row.col.f32.f16.f16.f32 "
        "{%0,%1,%2,%3}, {%4,%5,%6,%7}, {%8,%9}, {%0,%1,%2,%3};"
        : "+f"(d0), "+f"(d1), "+f"(d2), "+f"(d3)
        : "r"(a0), "r"(a1), "r"(a2), "r"(a3), "r"(b0), "r"(b1));
}

__global__ __launch_bounds__(128) void xform_hmma_kernel(
    const float4* __restrict__ X4,    // [N*16]
    const float4* __restrict__ W4,    // [64*16]
    int N)
{
    __shared__ __align__(16) __half Xh[64 * XS];
    __shared__ __align__(16) __half Wh[64 * XS];

    const int tid   = threadIdx.x;
    const int node0 = blockIdx.x * 64;

    for (int i = tid; i < 64 * 16; i += 128) {
        int r  = i >> 4;
        int cv = i & 15;
        float4 w = __ldg(W4 + i);
        *(__half2*)(Wh + r * XS + cv * 4)     = __floats2half2_rn(w.x, w.y);
        *(__half2*)(Wh + r * XS + cv * 4 + 2) = __floats2half2_rn(w.z, w.w);

        int n = node0 + r;
        float4 x = (n < N) ? __ldg(X4 + (size_t)n * 16 + cv)
                           : make_float4(0.f, 0.f, 0.f, 0.f);
        *(__half2*)(Xh + r * XS + cv * 4)     = __floats2half2_rn(x.x, x.y);
        *(__half2*)(Xh + r * XS + cv * 4 + 2) = __floats2half2_rn(x.z, x.w);
    }
    __syncthreads();

    const int warp = tid >> 5;
    const int lane = tid & 31;
    const int g    = lane >> 2;
    const int c    = (lane & 3) * 2;
    const int m0   = warp * 16;

    float acc[8][4];
#pragma unroll
    for (int nt = 0; nt < 8; nt++)
#pragma unroll
        for (int i = 0; i < 4; i++) acc[nt][i] = 0.f;

#pragma unroll
    for (int kt = 0; kt < 4; kt++) {
        const int k0 = kt * 16;
        unsigned a0 = *(const unsigned*)(Xh + (m0 + g)     * XS + k0 + c);
        unsigned a1 = *(const unsigned*)(Xh + (m0 + g + 8) * XS + k0 + c);
        unsigned a2 = *(const unsigned*)(Xh + (m0 + g)     * XS + k0 + c + 8);
        unsigned a3 = *(const unsigned*)(Xh + (m0 + g + 8) * XS + k0 + c + 8);
#pragma unroll
        for (int nt = 0; nt < 8; nt++) {
            unsigned b0 = *(const unsigned*)(Wh + (nt * 8 + g) * XS + k0 + c);
            unsigned b1 = *(const unsigned*)(Wh + (nt * 8 + g) * XS + k0 + c + 8);
            mma16816(acc[nt][0], acc[nt][1], acc[nt][2], acc[nt][3],
                     a0, a1, a2, a3, b0, b1);
        }
    }

    __half* Yh = (__half*)g_Yh;
    int rA = node0 + m0 + g;
    int rB = rA + 8;
#pragma unroll
    for (int nt = 0; nt < 8; nt++) {
        int colh = nt * 8 + c;
        if (rA < N)
            *(__half2*)(Yh + (size_t)rA * D + colh) =
                __floats2half2_rn(acc[nt][0], acc[nt][1]);
        if (rB < N)
            *(__half2*)(Yh + (size_t)rB * D + colh) =
                __floats2half2_rn(acc[nt][2], acc[nt][3]);
    }
}

// ---------------------------------------------------------------------------
// gather: out[n] = bias + sum over in-edges of val * Yh[col]
// 16 lanes per node, lane q owns uint2 chunk q. UNROLL-16 head (MLP=16,
// one batch covers the mean-degree node), then 8/4/1 tails.
// ---------------------------------------------------------------------------
__device__ __forceinline__ void fma_h4(float4& acc, float v, uint2 y) {
    __half2 h01 = *reinterpret_cast<__half2*>(&y.x);
    __half2 h23 = *reinterpret_cast<__half2*>(&y.y);
    float2 f01 = __half22float2(h01);
    float2 f23 = __half22float2(h23);
    acc.x += v * f01.x; acc.y += v * f01.y;
    acc.z += v * f23.x; acc.w += v * f23.y;
}

__global__ __launch_bounds__(256) void gather_bias_kernel(
    const float4* __restrict__ bias,   // [16]
    float4*       __restrict__ out,    // [N*16]
    int N)
{
    int t = blockIdx.x * 256 + threadIdx.x;
    int n = t >> 4;
    int q = t & 15;
    if (n >= N) return;

    int s = __ldg(&g_off[n]);
    int e = __ldg(&g_off[n + 1]);

    float4 acc = __ldg(bias + q);
    int j = s;

    for (; j + 16 <= e; j += 16) {
        int2 p[16];
#pragma unroll
        for (int u = 0; u < 16; u++) p[u] = g_edge[j + u];
        uint2 y[16];
#pragma unroll
        for (int u = 0; u < 16; u++)
            y[u] = __ldg(&g_Yh[(size_t)p[u].x * DV + q]);
#pragma unroll
        for (int u = 0; u < 16; u++)
            fma_h4(acc, __int_as_float(p[u].y), y[u]);
    }
    for (; j + 8 <= e; j += 8) {
        int2 p[8];
#pragma unroll
        for (int u = 0; u < 8; u++) p[u] = g_edge[j + u];
        uint2 y[8];
#pragma unroll
        for (int u = 0; u < 8; u++)
            y[u] = __ldg(&g_Yh[(size_t)p[u].x * DV + q]);
#pragma unroll
        for (int u = 0; u < 8; u++)
            fma_h4(acc, __int_as_float(p[u].y), y[u]);
    }
    for (; j + 4 <= e; j += 4) {
        int2 p[4];
#pragma unroll
        for (int u = 0; u < 4; u++) p[u] = g_edge[j + u];
        uint2 y[4];
#pragma unroll
        for (int u = 0; u < 4; u++)
            y[u] = __ldg(&g_Yh[(size_t)p[u].x * DV + q]);
#pragma unroll
        for (int u = 0; u < 4; u++)
            fma_h4(acc, __int_as_float(p[u].y), y[u]);
    }
    for (; j < e; j++) {
        int2 p = g_edge[j];
        uint2 y = __ldg(&g_Yh[(size_t)p.x * DV + q]);
        fma_h4(acc, __int_as_float(p.y), y);
    }
    out[(size_t)n * DV + q] = acc;
}

// ---------------------------------------------------------------------------
// Launch: inputs in metadata order: row, col, vals, X, weight, bias
// Plain 3-node serial graph (forking proven useless: all phases LSU-bound).
// ---------------------------------------------------------------------------
extern "C" void kernel_launch(void* const* d_in, const int* in_sizes, int n_in,
                              void* d_out, int out_size)
{
    const int*   row  = (const int*)  d_in[0];
    const int*   col  = (const int*)  d_in[1];
    const float* vals = (const float*)d_in[2];
    const float* X    = (const float*)d_in[3];
    const float* W    = (const float*)d_in[4];
    const float* bias = (const float*)d_in[5];
    float*       out  = (float*)d_out;

    int E = in_sizes[0];
    int N = in_sizes[3] / D;   // 100000

    xform_hmma_kernel<<<(N + 63) / 64, 128>>>(
        (const float4*)X, (const float4*)W, N);

    csr_build_kernel<<<NB, TB>>>(row, col, vals, E, N);

    int threads_gather = N * DV;
    gather_bias_kernel<<<(threads_gather + 255) / 256, 256>>>(
        (const float4*)bias, (float4*)out, N);
}